// round 5
// baseline (speedup 1.0000x reference)
#include <cuda_runtime.h>
#include <cstdint>

typedef unsigned long long ull;

// ---------------------------------------------------------------------------
// GCN 2-layer. R5:
//  - GEMM: FFMA2 (fma.rn.f32x2) with the register-safe R1 tile: 128x64 block,
//    4 rows x 8 cols per thread = acc[2][8] ull (32 regs, no spills).
//    W staged ONCE per block, pre-duplicated (w,w) so the broadcast operand
//    is a natural 16B shared load. 16 FFMA2 + 5 LDS.128 per k.
//  - gather-reduce: R4's branchless version (near L2-BW floor) unchanged.
// ---------------------------------------------------------------------------

#define MAX_NODES 100000
#define HID 64
#define CAP 64   // max in-degree (Binomial(1.6M, 1e-5): max ~36; pad<=+3)

__device__ float g_bufA[MAX_NODES * HID];
__device__ float g_bufB[MAX_NODES * HID];
__device__ int   g_cnt[MAX_NODES];
__device__ ull   g_buckets[(size_t)MAX_NODES * CAP];

#define FMA_F32X2(d, a, b, c) \
    asm("fma.rn.f32x2 %0, %1, %2, %3;" : "=l"(d) : "l"(a), "l"(b), "l"(c))

#define UNPACK_F32X2(lo, hi, v) \
    asm("mov.b64 {%0, %1}, %2;" : "=r"(lo), "=r"(hi) : "l"(v))

__device__ __forceinline__ ull pack2(float lo, float hi) {
    ull r;
    asm("mov.b64 %0, {%1, %2};" : "=l"(r) : "f"(lo), "f"(hi));
    return r;
}

// ---------------------------------------------------------------------------
// GEMM: C[N,64] = act(X[N,INDIM]) @ W[INDIM,64]
// 128 rows x 64 cols per block, 256 threads, thread tile 4x8 (2 f32x2 row
// pairs x 8 cols). W duplicated in smem; X chunks (8-deep) double-buffered.
// ---------------------------------------------------------------------------
template <int INDIM, bool RELU_IN>
__global__ __launch_bounds__(256) void gemm_kernel(
    const float* __restrict__ X, const float* __restrict__ W,
    float* __restrict__ C, int N)
{
    __shared__ float w_d[INDIM][128];    // duplicated: w_d[k][2j]=w_d[k][2j+1]=W[k][j]
    __shared__ float x_s[2][8][132];     // stride 132: conflict-free staging

    const int tid = threadIdx.x;
    const int row0 = blockIdx.x * 128;
    const int rg = tid >> 3;          // 0..31
    const int cg = tid & 7;           // 0..7
    const int r0 = rg * 4;
    const int c0 = cg * 8;
    const int kk = tid & 7;           // k within chunk
    const int rbase = tid >> 3;       // 0..31

    // Stage W once, duplicated (float2 source -> two ull stores each)
    for (int i = tid; i < INDIM * 32; i += 256) {
        int k = i >> 5, j2 = i & 31;
        float2 v = ((const float2*)W)[(size_t)k * 32 + j2];
        *(ull*)&w_d[k][4 * j2]     = pack2(v.x, v.x);
        *(ull*)&w_d[k][4 * j2 + 2] = pack2(v.y, v.y);
    }

    ull acc[2][8];
#pragma unroll
    for (int i = 0; i < 2; ++i)
#pragma unroll
        for (int j = 0; j < 8; ++j) acc[i][j] = 0ULL;

    const int NCH = INDIM / 8;

    // Prologue: load chunk 0
#pragma unroll
    for (int it = 0; it < 4; ++it) {
        int r = rbase + it * 32;
        int gr = min(row0 + r, N - 1);
        float v = X[(size_t)gr * INDIM + kk];
        if (RELU_IN) v = fmaxf(v, 0.f);
        x_s[0][kk][r] = v;
    }
    __syncthreads();

    for (int c = 0; c < NCH; ++c) {
        const int cur = c & 1;
        if (c + 1 < NCH) {
            const int k0n = (c + 1) * 8;
#pragma unroll
            for (int it = 0; it < 4; ++it) {
                int r = rbase + it * 32;
                int gr = min(row0 + r, N - 1);
                float v = X[(size_t)gr * INDIM + k0n + kk];
                if (RELU_IN) v = fmaxf(v, 0.f);
                x_s[cur ^ 1][kk][r] = v;
            }
        }
        const int k0 = c * 8;
#pragma unroll
        for (int k = 0; k < 8; ++k) {
            // 2 row-pairs: one 16B load (rows r0..r0+3)
            ulonglong2 xv = *(const ulonglong2*)&x_s[cur][k][r0];
            ull xp0 = xv.x, xp1 = xv.y;
            // 8 duplicated w pairs: 64B = 4 x 16B loads
            ulonglong2 wv0 = *(const ulonglong2*)&w_d[k0 + k][2 * c0];
            ulonglong2 wv1 = *(const ulonglong2*)&w_d[k0 + k][2 * c0 + 4];
            ulonglong2 wv2 = *(const ulonglong2*)&w_d[k0 + k][2 * c0 + 8];
            ulonglong2 wv3 = *(const ulonglong2*)&w_d[k0 + k][2 * c0 + 12];
            ull wp[8] = {wv0.x, wv0.y, wv1.x, wv1.y, wv2.x, wv2.y, wv3.x, wv3.y};
#pragma unroll
            for (int j = 0; j < 8; ++j) {
                FMA_F32X2(acc[0][j], xp0, wp[j], acc[0][j]);
                FMA_F32X2(acc[1][j], xp1, wp[j], acc[1][j]);
            }
        }
        __syncthreads();
    }

    // Store: pair i covers rows (r0+2i, r0+2i+1)
#pragma unroll
    for (int i = 0; i < 2; ++i) {
        unsigned lo[8], hi[8];
#pragma unroll
        for (int j = 0; j < 8; ++j) UNPACK_F32X2(lo[j], hi[j], acc[i][j]);
        int gr = row0 + r0 + 2 * i;
        if (gr < N) {
            float4 a = make_float4(__uint_as_float(lo[0]), __uint_as_float(lo[1]),
                                   __uint_as_float(lo[2]), __uint_as_float(lo[3]));
            float4 b = make_float4(__uint_as_float(lo[4]), __uint_as_float(lo[5]),
                                   __uint_as_float(lo[6]), __uint_as_float(lo[7]));
            *(float4*)&C[(size_t)gr * 64 + c0]     = a;
            *(float4*)&C[(size_t)gr * 64 + c0 + 4] = b;
        }
        if (gr + 1 < N) {
            float4 a = make_float4(__uint_as_float(hi[0]), __uint_as_float(hi[1]),
                                   __uint_as_float(hi[2]), __uint_as_float(hi[3]));
            float4 b = make_float4(__uint_as_float(hi[4]), __uint_as_float(hi[5]),
                                   __uint_as_float(hi[6]), __uint_as_float(hi[7]));
            *(float4*)&C[(size_t)(gr + 1) * 64 + c0]     = a;
            *(float4*)&C[(size_t)(gr + 1) * 64 + c0 + 4] = b;
        }
    }
}

// ---------------------------------------------------------------------------
__global__ void zero_cnt_kernel(int* __restrict__ cnt, int N)
{
    int i = blockIdx.x * blockDim.x + threadIdx.x;
    if (i < N) cnt[i] = 0;
}

// Bucket placement: entry = (src*256) | (weight_bits << 32).
__global__ __launch_bounds__(256) void place_kernel(
    const int* __restrict__ src, const int* __restrict__ dst,
    const float* __restrict__ ew,
    int* __restrict__ cnt, ull* __restrict__ buckets, int E)
{
    int e = blockIdx.x * blockDim.x + threadIdx.x;
    if (e >= E) return;
    int d = dst[e];
    int pos = atomicAdd(&cnt[d], 1);
    if (pos < CAP) {
        ull v = (unsigned)(src[e] * 256)
              | ((ull)__float_as_uint(ew[e]) << 32);
        buckets[(size_t)d * CAP + pos] = v;
    }
}

// Pad each bucket to a multiple of 4 with zero-weight entries.
__global__ void pad_kernel(int* __restrict__ cnt, ull* __restrict__ buckets, int N)
{
    int n = blockIdx.x * blockDim.x + threadIdx.x;
    if (n >= N) return;
    int deg = min(cnt[n], CAP);
    int pdeg = (deg + 3) & ~3;
    ull* b = buckets + (size_t)n * CAP;
#pragma unroll
    for (int i = 0; i < 3; ++i)
        if (deg + i < pdeg) b[deg + i] = 0ULL;
    cnt[n] = pdeg;
}

// ---------------------------------------------------------------------------
// Gather-reduce: 16 lanes per node, float4 per lane, branchless inner loop.
// ---------------------------------------------------------------------------
__global__ __launch_bounds__(256) void gather_reduce_kernel(
    const ull* __restrict__ buckets,
    const int* __restrict__ cnt,
    const float* __restrict__ h,
    const float* __restrict__ bias,
    float* __restrict__ out, int N)
{
    int node = (blockIdx.x * 256 + threadIdx.x) >> 4;
    int lane = threadIdx.x & 15;
    if (node >= N) return;

    int deg = cnt[node];                 // multiple of 4, <= CAP
    float4 acc = *(const float4*)(bias + lane * 4);
    const ull* b = buckets + (size_t)node * CAP;
    const char* hb = (const char*)h + lane * 16;

    for (int j = 0; j < deg; j += 4) {
#pragma unroll
        for (int k = 0; k < 4; ++k) {
            ull ej = __ldg(&b[j + k]);                   // broadcast across 16 lanes
            float w = __uint_as_float((unsigned)(ej >> 32));
            unsigned off = (unsigned)ej;                  // src*256
            float4 hv = *(const float4*)(hb + off);
            acc.x = fmaf(w, hv.x, acc.x);
            acc.y = fmaf(w, hv.y, acc.y);
            acc.z = fmaf(w, hv.z, acc.z);
            acc.w = fmaf(w, hv.w, acc.w);
        }
    }
    *(float4*)(out + (size_t)node * 64 + lane * 4) = acc;
}

// ---------------------------------------------------------------------------
extern "C" void kernel_launch(void* const* d_in, const int* in_sizes, int n_in,
                              void* d_out, int out_size)
{
    const float* x   = (const float*)d_in[0];
    const int*   ei  = (const int*)d_in[1];
    const float* ew  = (const float*)d_in[2];
    const float* w1  = (const float*)d_in[3];
    const float* b1  = (const float*)d_in[4];
    const float* w2  = (const float*)d_in[5];
    const float* b2  = (const float*)d_in[6];
    float* out = (float*)d_out;

    const int N = in_sizes[0] / 128;       // 100000
    const int E = in_sizes[2];             // 1600000

    float* bufA = nullptr;
    float* bufB = nullptr;
    int*   cnt  = nullptr;
    ull*   buckets = nullptr;
    cudaGetSymbolAddress((void**)&bufA, g_bufA);
    cudaGetSymbolAddress((void**)&bufB, g_bufB);
    cudaGetSymbolAddress((void**)&cnt, g_cnt);
    cudaGetSymbolAddress((void**)&buckets, g_buckets);

    const int gemm_blocks = (N + 127) / 128;
    const int gr_blocks   = (N * 16 + 255) / 256;

    // Indexing pass (shared by both layers)
    zero_cnt_kernel<<<(N + 255) / 256, 256>>>(cnt, N);
    place_kernel<<<(E + 255) / 256, 256>>>(ei, ei + E, ew, cnt, buckets, E);
    pad_kernel<<<(N + 255) / 256, 256>>>(cnt, buckets, N);

    // Layer 1
    gemm_kernel<128, false><<<gemm_blocks, 256>>>(x, w1, bufA, N);
    gather_reduce_kernel<<<gr_blocks, 256>>>(buckets, cnt, bufA, b1, bufB, N);

    // Layer 2 (ReLU fused into GEMM input load)
    gemm_kernel<64, true><<<gemm_blocks, 256>>>(bufB, w2, bufA, N);
    gather_reduce_kernel<<<gr_blocks, 256>>>(buckets, cnt, bufA, b2, out, N);
}

// round 6
// speedup vs baseline: 2.2768x; 2.2768x over previous
#include <cuda_runtime.h>
#include <cuda_fp16.h>
#include <cstdint>

typedef unsigned long long ull;

// ---------------------------------------------------------------------------
// GCN 2-layer. R6 = R4 (best, 213us) + fp16 hidden states for the gather:
//  - GEMM (R4's proven register-tiled fp32 kernel) accumulates fp32, stores
//    h as __half (128B/row) -> gather L2 traffic halves.
//  - gather-reduce: branchless, 16 lanes/node, 8B (4 halfs) per lane,
//    fp32 accumulation, fp32 output. Bucket entry = (src*128 | w<<32).
// ---------------------------------------------------------------------------

#define MAX_NODES 100000
#define HID 64
#define CAP 64   // max in-degree (Binomial(1.6M, 1e-5): max ~36; pad<=+3)

__device__ __half g_bufH[MAX_NODES * HID];   // h1 then h2 (fp16)
__device__ float  g_bufB[MAX_NODES * HID];   // agg1 (fp32)
__device__ int    g_cnt[MAX_NODES];
__device__ ull    g_buckets[(size_t)MAX_NODES * CAP];

// ---------------------------------------------------------------------------
// GEMM: C_half[N,64] = act(X[N,INDIM]) @ W[INDIM,64]
// 128 rows x 64 cols per block, 256 threads, thread tile 4x8, fp32 math.
// W fully staged; X chunks (8-deep) double-buffered. (R4 body, half store.)
// ---------------------------------------------------------------------------
template <int INDIM, bool RELU_IN>
__global__ __launch_bounds__(256) void gemm_kernel(
    const float* __restrict__ X, const float* __restrict__ W,
    __half* __restrict__ C, int N)
{
    __shared__ float w_s[INDIM][64];
    __shared__ float x_s[2][8][132];

    const int tid = threadIdx.x;
    const int row0 = blockIdx.x * 128;
    const int rg = tid >> 3;
    const int cg = tid & 7;
    const int r0 = rg * 4;
    const int c0 = cg * 8;
    const int kk = tid & 7;
    const int rbase = tid >> 3;

    for (int i = tid; i < INDIM * 64 / 4; i += 256)
        ((float4*)w_s)[i] = ((const float4*)W)[i];

    float acc[4][8];
#pragma unroll
    for (int i = 0; i < 4; ++i)
#pragma unroll
        for (int j = 0; j < 8; ++j) acc[i][j] = 0.f;

    const int NCH = INDIM / 8;

#pragma unroll
    for (int it = 0; it < 4; ++it) {
        int r = rbase + it * 32;
        int gr = min(row0 + r, N - 1);
        float v = X[(size_t)gr * INDIM + kk];
        if (RELU_IN) v = fmaxf(v, 0.f);
        x_s[0][kk][r] = v;
    }
    __syncthreads();

    for (int c = 0; c < NCH; ++c) {
        const int cur = c & 1;
        if (c + 1 < NCH) {
            const int k0n = (c + 1) * 8;
#pragma unroll
            for (int it = 0; it < 4; ++it) {
                int r = rbase + it * 32;
                int gr = min(row0 + r, N - 1);
                float v = X[(size_t)gr * INDIM + k0n + kk];
                if (RELU_IN) v = fmaxf(v, 0.f);
                x_s[cur ^ 1][kk][r] = v;
            }
        }
        const int k0 = c * 8;
#pragma unroll
        for (int k = 0; k < 8; ++k) {
            float4 xv = *(const float4*)&x_s[cur][k][r0];
            float xr[4] = {xv.x, xv.y, xv.z, xv.w};
            float wc[8];
            *(float4*)&wc[0] = *(const float4*)&w_s[k0 + k][c0];
            *(float4*)&wc[4] = *(const float4*)&w_s[k0 + k][c0 + 4];
#pragma unroll
            for (int i = 0; i < 4; ++i)
#pragma unroll
                for (int j = 0; j < 8; ++j)
                    acc[i][j] = fmaf(xr[i], wc[j], acc[i][j]);
        }
        __syncthreads();
    }

    // Store as fp16: 8 cols -> 16B per row per thread
#pragma unroll
    for (int i = 0; i < 4; ++i) {
        int gr = row0 + r0 + i;
        if (gr < N) {
            __half2 h0 = __floats2half2_rn(acc[i][0], acc[i][1]);
            __half2 h1 = __floats2half2_rn(acc[i][2], acc[i][3]);
            __half2 h2 = __floats2half2_rn(acc[i][4], acc[i][5]);
            __half2 h3 = __floats2half2_rn(acc[i][6], acc[i][7]);
            uint4 v;
            v.x = *(unsigned*)&h0;
            v.y = *(unsigned*)&h1;
            v.z = *(unsigned*)&h2;
            v.w = *(unsigned*)&h3;
            *(uint4*)(C + (size_t)gr * 64 + c0) = v;
        }
    }
}

// ---------------------------------------------------------------------------
__global__ void zero_cnt_kernel(int* __restrict__ cnt, int N)
{
    int i = blockIdx.x * blockDim.x + threadIdx.x;
    if (i < N) cnt[i] = 0;
}

// Bucket placement: entry = (src*128) | (weight_bits << 32).
// src*128 = byte offset of row src in the fp16 h buffer (64 halfs/row).
__global__ __launch_bounds__(256) void place_kernel(
    const int* __restrict__ src, const int* __restrict__ dst,
    const float* __restrict__ ew,
    int* __restrict__ cnt, ull* __restrict__ buckets, int E)
{
    int e = blockIdx.x * blockDim.x + threadIdx.x;
    if (e >= E) return;
    int d = dst[e];
    int pos = atomicAdd(&cnt[d], 1);
    if (pos < CAP) {
        ull v = (unsigned)(src[e] * 128)
              | ((ull)__float_as_uint(ew[e]) << 32);
        buckets[(size_t)d * CAP + pos] = v;
    }
}

// Pad each bucket to a multiple of 4 with zero-weight entries.
__global__ void pad_kernel(int* __restrict__ cnt, ull* __restrict__ buckets, int N)
{
    int n = blockIdx.x * blockDim.x + threadIdx.x;
    if (n >= N) return;
    int deg = min(cnt[n], CAP);
    int pdeg = (deg + 3) & ~3;
    ull* b = buckets + (size_t)n * CAP;
#pragma unroll
    for (int i = 0; i < 3; ++i)
        if (deg + i < pdeg) b[deg + i] = 0ULL;
    cnt[n] = pdeg;
}

// ---------------------------------------------------------------------------
// Gather-reduce: 16 lanes per node, 8B (4 halfs) per lane, branchless.
// out[n] = bias + sum_e w_e * h[src_e], fp32 accumulation & output.
// ---------------------------------------------------------------------------
__global__ __launch_bounds__(256) void gather_reduce_kernel(
    const ull* __restrict__ buckets,
    const int* __restrict__ cnt,
    const __half* __restrict__ h,
    const float* __restrict__ bias,
    float* __restrict__ out, int N)
{
    int node = (blockIdx.x * 256 + threadIdx.x) >> 4;
    int lane = threadIdx.x & 15;
    if (node >= N) return;

    int deg = cnt[node];                 // multiple of 4, <= CAP
    float4 acc = *(const float4*)(bias + lane * 4);
    const ull* b = buckets + (size_t)node * CAP;
    const char* hb = (const char*)h + lane * 8;

    for (int j = 0; j < deg; j += 4) {
#pragma unroll
        for (int k = 0; k < 4; ++k) {
            ull ej = __ldg(&b[j + k]);                   // broadcast across lanes
            float w = __uint_as_float((unsigned)(ej >> 32));
            unsigned off = (unsigned)ej;                  // src*128
            uint2 raw = *(const uint2*)(hb + off);
            __half2 p01 = *(__half2*)&raw.x;
            __half2 p23 = *(__half2*)&raw.y;
            float2 f01 = __half22float2(p01);
            float2 f23 = __half22float2(p23);
            acc.x = fmaf(w, f01.x, acc.x);
            acc.y = fmaf(w, f01.y, acc.y);
            acc.z = fmaf(w, f23.x, acc.z);
            acc.w = fmaf(w, f23.y, acc.w);
        }
    }
    *(float4*)(out + (size_t)node * 64 + lane * 4) = acc;
}

// ---------------------------------------------------------------------------
extern "C" void kernel_launch(void* const* d_in, const int* in_sizes, int n_in,
                              void* d_out, int out_size)
{
    const float* x   = (const float*)d_in[0];
    const int*   ei  = (const int*)d_in[1];
    const float* ew  = (const float*)d_in[2];
    const float* w1  = (const float*)d_in[3];
    const float* b1  = (const float*)d_in[4];
    const float* w2  = (const float*)d_in[5];
    const float* b2  = (const float*)d_in[6];
    float* out = (float*)d_out;

    const int N = in_sizes[0] / 128;       // 100000
    const int E = in_sizes[2];             // 1600000

    __half* bufH = nullptr;
    float*  bufB = nullptr;
    int*    cnt  = nullptr;
    ull*    buckets = nullptr;
    cudaGetSymbolAddress((void**)&bufH, g_bufH);
    cudaGetSymbolAddress((void**)&bufB, g_bufB);
    cudaGetSymbolAddress((void**)&cnt, g_cnt);
    cudaGetSymbolAddress((void**)&buckets, g_buckets);

    const int gemm_blocks = (N + 127) / 128;
    const int gr_blocks   = (N * 16 + 255) / 256;

    // Indexing pass (shared by both layers)
    zero_cnt_kernel<<<(N + 255) / 256, 256>>>(cnt, N);
    place_kernel<<<(E + 255) / 256, 256>>>(ei, ei + E, ew, cnt, buckets, E);
    pad_kernel<<<(N + 255) / 256, 256>>>(cnt, buckets, N);

    // Layer 1
    gemm_kernel<128, false><<<gemm_blocks, 256>>>(x, w1, bufH, N);
    gather_reduce_kernel<<<gr_blocks, 256>>>(buckets, cnt, bufH, b1, bufB, N);

    // Layer 2 (ReLU fused into GEMM input load)
    gemm_kernel<64, true><<<gemm_blocks, 256>>>(bufB, w2, bufH, N);
    gather_reduce_kernel<<<gr_blocks, 256>>>(buckets, cnt, bufH, b2, out, N);
}

// round 7
// speedup vs baseline: 3.5183x; 1.5452x over previous
#include <cuda_runtime.h>
#include <cuda_fp16.h>
#include <cstdint>

typedef unsigned long long ull;

// ---------------------------------------------------------------------------
// GCN 2-layer. R7 = R6 + tensor-core GEMMs:
//  - GEMM: mma.sync.aligned.m16n8k16.row.col.f32.f16.f16.f32 (HMMA).
//    X/W converted fp32->fp16 during smem staging, fp32 accumulate,
//    fp16 h output (gather already consumes fp16). Explicit fragment
//    loads (LDS.32, conflict-free: row stride = 4 banks mod 32).
//  - gather-reduce / place / pad: unchanged from R6 (best: 190.7us).
// ---------------------------------------------------------------------------

#define MAX_NODES 100000
#define HID 64
#define CAP 64   // max in-degree (Binomial(1.6M, 1e-5): max ~36; pad<=+3)

__device__ __half g_bufH[MAX_NODES * HID];   // h1 then h2 (fp16)
__device__ float  g_bufB[MAX_NODES * HID];   // agg1 (fp32)
__device__ int    g_cnt[MAX_NODES];
__device__ ull    g_buckets[(size_t)MAX_NODES * CAP];

__device__ __forceinline__ void mma16816(
    float& d0, float& d1, float& d2, float& d3,
    unsigned a0, unsigned a1, unsigned a2, unsigned a3,
    unsigned b0, unsigned b1)
{
    asm("mma.sync.aligned.m16n8k16.row.col.f32.f16.f16.f32 "
        "{%0,%1,%2,%3}, {%4,%5,%6,%7}, {%8,%9}, {%0,%1,%2,%3};"
        : "+f"(d0), "+f"(d1), "+f"(d2), "+f"(d3)
        : "r"(a0), "r"(a1), "r"(a2), "r"(a3), "r"(b0), "r"(b1));
}

// ---------------------------------------------------------------------------
// Tensor-core GEMM: C_half[N,64] = act(X[N,INDIM]) @ W[INDIM,64]
// CTA: 128 rows x 64 cols, 256 threads (8 warps: 4 over M, 2 over N).
// Warp tile 32x32 = 2(m16) x 4(n8) frags. K chunked by 64 (fp16 staging).
// ---------------------------------------------------------------------------
template <int INDIM, bool RELU_IN>
__global__ __launch_bounds__(256) void mma_gemm_kernel(
    const float* __restrict__ X, const float* __restrict__ W,
    __half* __restrict__ C, int N)
{
    __shared__ __half xs[128][72];          // one 64-k chunk, +8 pad
    __shared__ __half ws[64][INDIM + 8];    // full W^T, +8 pad

    const int tid  = threadIdx.x;
    const int lane = tid & 31;
    const int wid  = tid >> 5;
    const int warp_m = wid & 3;            // 0..3 -> 32-row block
    const int warp_n = wid >> 2;           // 0..1 -> 32-col block
    const int lr = lane >> 2;              // 0..7
    const int lc = (lane & 3) * 2;         // 0,2,4,6
    const int row0 = blockIdx.x * 128;

    // Stage W^T (fp16) once: ws[n][k] = W[k*64+n]
    for (int i = tid; i < 64 * INDIM; i += 256) {
        int k = i >> 6, n = i & 63;
        ws[n][k] = __float2half_rn(W[k * 64 + n]);
    }

    float acc[2][4][4];
#pragma unroll
    for (int mt = 0; mt < 2; ++mt)
#pragma unroll
        for (int nt = 0; nt < 4; ++nt)
#pragma unroll
            for (int q = 0; q < 4; ++q) acc[mt][nt][q] = 0.f;

    const int srow = tid >> 4;             // 0..15
    const int sc4  = tid & 15;             // float4 index within 64-col chunk

    for (int kc = 0; kc < INDIM / 64; ++kc) {
        __syncthreads();
        // Stage X chunk [128 rows x 64 k] as fp16
#pragma unroll
        for (int it = 0; it < 8; ++it) {
            int r = srow + it * 16;
            int gr = min(row0 + r, N - 1);
            float4 v = *(const float4*)&X[(size_t)gr * INDIM + kc * 64 + sc4 * 4];
            if (RELU_IN) {
                v.x = fmaxf(v.x, 0.f); v.y = fmaxf(v.y, 0.f);
                v.z = fmaxf(v.z, 0.f); v.w = fmaxf(v.w, 0.f);
            }
            __half2 p0 = __floats2half2_rn(v.x, v.y);
            __half2 p1 = __floats2half2_rn(v.z, v.w);
            uint2 pk;
            pk.x = *(unsigned*)&p0;
            pk.y = *(unsigned*)&p1;
            *(uint2*)&xs[r][sc4 * 4] = pk;
        }
        __syncthreads();

#pragma unroll
        for (int k16 = 0; k16 < 4; ++k16) {
            const int k0 = k16 * 16;            // within xs chunk
            const int kg = kc * 64 + k0;        // within ws
            // A fragments (2 m16 tiles)
            unsigned a[2][4];
#pragma unroll
            for (int mt = 0; mt < 2; ++mt) {
                int ar = warp_m * 32 + mt * 16 + lr;
                a[mt][0] = *(const unsigned*)&xs[ar][k0 + lc];
                a[mt][1] = *(const unsigned*)&xs[ar + 8][k0 + lc];
                a[mt][2] = *(const unsigned*)&xs[ar][k0 + lc + 8];
                a[mt][3] = *(const unsigned*)&xs[ar + 8][k0 + lc + 8];
            }
            // B fragments (4 n8 tiles)
            unsigned b[4][2];
#pragma unroll
            for (int nt = 0; nt < 4; ++nt) {
                int bn = warp_n * 32 + nt * 8 + lr;
                b[nt][0] = *(const unsigned*)&ws[bn][kg + lc];
                b[nt][1] = *(const unsigned*)&ws[bn][kg + lc + 8];
            }
#pragma unroll
            for (int mt = 0; mt < 2; ++mt)
#pragma unroll
                for (int nt = 0; nt < 4; ++nt)
                    mma16816(acc[mt][nt][0], acc[mt][nt][1],
                             acc[mt][nt][2], acc[mt][nt][3],
                             a[mt][0], a[mt][1], a[mt][2], a[mt][3],
                             b[nt][0], b[nt][1]);
        }
    }

    // Epilogue: fp32 acc -> fp16 store.
    // c0,c1 -> (row, col), (row, col+1); c2,c3 -> (row+8, ...)
#pragma unroll
    for (int mt = 0; mt < 2; ++mt) {
#pragma unroll
        for (int nt = 0; nt < 4; ++nt) {
            int row = row0 + warp_m * 32 + mt * 16 + lr;
            int col = warp_n * 32 + nt * 8 + lc;
            __half2 lo = __floats2half2_rn(acc[mt][nt][0], acc[mt][nt][1]);
            __half2 hi = __floats2half2_rn(acc[mt][nt][2], acc[mt][nt][3]);
            if (row < N)
                *(__half2*)(C + (size_t)row * 64 + col) = lo;
            if (row + 8 < N)
                *(__half2*)(C + (size_t)(row + 8) * 64 + col) = hi;
        }
    }
}

// ---------------------------------------------------------------------------
__global__ void zero_cnt_kernel(int* __restrict__ cnt, int N)
{
    int i = blockIdx.x * blockDim.x + threadIdx.x;
    if (i < N) cnt[i] = 0;
}

// Bucket placement: entry = (src*128) | (weight_bits << 32).
// src*128 = byte offset of row src in the fp16 h buffer (64 halfs/row).
__global__ __launch_bounds__(256) void place_kernel(
    const int* __restrict__ src, const int* __restrict__ dst,
    const float* __restrict__ ew,
    int* __restrict__ cnt, ull* __restrict__ buckets, int E)
{
    int e = blockIdx.x * blockDim.x + threadIdx.x;
    if (e >= E) return;
    int d = dst[e];
    int pos = atomicAdd(&cnt[d], 1);
    if (pos < CAP) {
        ull v = (unsigned)(src[e] * 128)
              | ((ull)__float_as_uint(ew[e]) << 32);
        buckets[(size_t)d * CAP + pos] = v;
    }
}

// Pad each bucket to a multiple of 4 with zero-weight entries.
__global__ void pad_kernel(int* __restrict__ cnt, ull* __restrict__ buckets, int N)
{
    int n = blockIdx.x * blockDim.x + threadIdx.x;
    if (n >= N) return;
    int deg = min(cnt[n], CAP);
    int pdeg = (deg + 3) & ~3;
    ull* b = buckets + (size_t)n * CAP;
#pragma unroll
    for (int i = 0; i < 3; ++i)
        if (deg + i < pdeg) b[deg + i] = 0ULL;
    cnt[n] = pdeg;
}

// ---------------------------------------------------------------------------
// Gather-reduce: 16 lanes per node, 8B (4 halfs) per lane, branchless.
// out[n] = bias + sum_e w_e * h[src_e], fp32 accumulation & output.
// ---------------------------------------------------------------------------
__global__ __launch_bounds__(256) void gather_reduce_kernel(
    const ull* __restrict__ buckets,
    const int* __restrict__ cnt,
    const __half* __restrict__ h,
    const float* __restrict__ bias,
    float* __restrict__ out, int N)
{
    int node = (blockIdx.x * 256 + threadIdx.x) >> 4;
    int lane = threadIdx.x & 15;
    if (node >= N) return;

    int deg = cnt[node];                 // multiple of 4, <= CAP
    float4 acc = *(const float4*)(bias + lane * 4);
    const ull* b = buckets + (size_t)node * CAP;
    const char* hb = (const char*)h + lane * 8;

    for (int j = 0; j < deg; j += 4) {
#pragma unroll
        for (int k = 0; k < 4; ++k) {
            ull ej = __ldg(&b[j + k]);                   // broadcast across lanes
            float w = __uint_as_float((unsigned)(ej >> 32));
            unsigned off = (unsigned)ej;                  // src*128
            uint2 raw = *(const uint2*)(hb + off);
            __half2 p01 = *(__half2*)&raw.x;
            __half2 p23 = *(__half2*)&raw.y;
            float2 f01 = __half22float2(p01);
            float2 f23 = __half22float2(p23);
            acc.x = fmaf(w, f01.x, acc.x);
            acc.y = fmaf(w, f01.y, acc.y);
            acc.z = fmaf(w, f23.x, acc.z);
            acc.w = fmaf(w, f23.y, acc.w);
        }
    }
    *(float4*)(out + (size_t)node * 64 + lane * 4) = acc;
}

// ---------------------------------------------------------------------------
extern "C" void kernel_launch(void* const* d_in, const int* in_sizes, int n_in,
                              void* d_out, int out_size)
{
    const float* x   = (const float*)d_in[0];
    const int*   ei  = (const int*)d_in[1];
    const float* ew  = (const float*)d_in[2];
    const float* w1  = (const float*)d_in[3];
    const float* b1  = (const float*)d_in[4];
    const float* w2  = (const float*)d_in[5];
    const float* b2  = (const float*)d_in[6];
    float* out = (float*)d_out;

    const int N = in_sizes[0] / 128;       // 100000
    const int E = in_sizes[2];             // 1600000

    __half* bufH = nullptr;
    float*  bufB = nullptr;
    int*    cnt  = nullptr;
    ull*    buckets = nullptr;
    cudaGetSymbolAddress((void**)&bufH, g_bufH);
    cudaGetSymbolAddress((void**)&bufB, g_bufB);
    cudaGetSymbolAddress((void**)&cnt, g_cnt);
    cudaGetSymbolAddress((void**)&buckets, g_buckets);

    const int gemm_blocks = (N + 127) / 128;
    const int gr_blocks   = (N * 16 + 255) / 256;

    // Indexing pass (shared by both layers)
    zero_cnt_kernel<<<(N + 255) / 256, 256>>>(cnt, N);
    place_kernel<<<(E + 255) / 256, 256>>>(ei, ei + E, ew, cnt, buckets, E);
    pad_kernel<<<(N + 255) / 256, 256>>>(cnt, buckets, N);

    // Layer 1
    mma_gemm_kernel<128, false><<<gemm_blocks, 256>>>(x, w1, bufH, N);
    gather_reduce_kernel<<<gr_blocks, 256>>>(buckets, cnt, bufH, b1, bufB, N);

    // Layer 2 (ReLU fused into GEMM staging)
    mma_gemm_kernel<64, true><<<gemm_blocks, 256>>>(bufB, w2, bufH, N);
    gather_reduce_kernel<<<gr_blocks, 256>>>(buckets, cnt, bufH, b2, out, N);
}

// round 8
// speedup vs baseline: 3.5720x; 1.0153x over previous
#include <cuda_runtime.h>
#include <cuda_fp16.h>
#include <cstdint>

typedef unsigned long long ull;

// ---------------------------------------------------------------------------
// GCN 2-layer. R8 = R7 (123.4us) + pipelined MMA GEMM + fp16 inter-layer:
//  - GEMM: m16n8k16 HMMA, 32-k chunks double-buffered; chunk0 prefetched to
//    registers BEFORE W staging (overlap both DRAM round trips); chunk k+1
//    prefetched during compute of chunk k. One sync per chunk.
//  - gather1 applies ReLU and writes agg1 as fp16 -> gemm64 reads fp16
//    (removes the 25.6MB fp32 agg round trip entirely).
//  - place/pad/zero + branchless gather core unchanged.
// ---------------------------------------------------------------------------

#define MAX_NODES 100000
#define HID 64
#define CAP 64   // max in-degree (Binomial(1.6M, 1e-5): max ~36; pad<=+3)

__device__ __half g_bufH[MAX_NODES * HID];   // h1 then h2 (fp16)
__device__ __half g_bufA[MAX_NODES * HID];   // relu(agg1) (fp16)
__device__ int    g_cnt[MAX_NODES];
__device__ ull    g_buckets[(size_t)MAX_NODES * CAP];

__device__ __forceinline__ void mma16816(
    float& d0, float& d1, float& d2, float& d3,
    unsigned a0, unsigned a1, unsigned a2, unsigned a3,
    unsigned b0, unsigned b1)
{
    asm("mma.sync.aligned.m16n8k16.row.col.f32.f16.f16.f32 "
        "{%0,%1,%2,%3}, {%4,%5,%6,%7}, {%8,%9}, {%0,%1,%2,%3};"
        : "+f"(d0), "+f"(d1), "+f"(d2), "+f"(d3)
        : "r"(a0), "r"(a1), "r"(a2), "r"(a3), "r"(b0), "r"(b1));
}

template <typename T> struct Sel;
template <> struct Sel<float>  { typedef float4 Vec; };
template <> struct Sel<__half> { typedef uint2  Vec; };

__device__ __forceinline__ void store4h(__half* p, float4 v) {
    __half2 a = __floats2half2_rn(v.x, v.y);
    __half2 b = __floats2half2_rn(v.z, v.w);
    uint2 u; u.x = *(unsigned*)&a; u.y = *(unsigned*)&b;
    *(uint2*)p = u;
}
__device__ __forceinline__ void store4h(__half* p, uint2 v) { *(uint2*)p = v; }

// ---------------------------------------------------------------------------
// Pipelined tensor-core GEMM: C_half[N,64] = X[N,INDIM] @ W[INDIM,64]
// CTA 128 rows x 64 cols, 256 threads (8 warps: 4 over M, 2 over N).
// K chunked by 32, double-buffered, register prefetch.
// ---------------------------------------------------------------------------
template <int INDIM, typename TIN>
__global__ __launch_bounds__(256) void mma_gemm_kernel(
    const TIN* __restrict__ X, const float* __restrict__ W,
    __half* __restrict__ C, int N)
{
    constexpr int NCH = INDIM / 32;
    __shared__ __half xs[2][128][40];       // 32-k chunk, +8 pad (stride 20 banks)
    __shared__ __half ws[64][INDIM + 8];    // W^T, stride 4 banks mod 32

    const int tid  = threadIdx.x;
    const int lane = tid & 31;
    const int wid  = tid >> 5;
    const int warp_m = wid & 3;
    const int warp_n = wid >> 2;
    const int lr = lane >> 2;               // 0..7
    const int lc = (lane & 3) * 2;          // 0,2,4,6
    const int row0 = blockIdx.x * 128;
    const int srow = tid >> 3;              // 0..31
    const int sc2  = tid & 7;               // quad index within 32-col chunk

    typedef typename Sel<TIN>::Vec LVec;
    LVec v[4];

    // Prefetch chunk 0 into registers (LDGs in flight during W staging)
    int gr[4];
#pragma unroll
    for (int it = 0; it < 4; ++it) {
        gr[it] = min(row0 + srow + it * 32, N - 1);
        v[it] = *(const LVec*)&X[(size_t)gr[it] * INDIM + sc2 * 4];
    }

    // Stage W^T (fp16): ws[n][k] = W[k*64+n]
    for (int i = tid; i < 64 * INDIM; i += 256) {
        int k = i >> 6, n = i & 63;
        ws[n][k] = __float2half_rn(W[k * 64 + n]);
    }

    // Store chunk 0
#pragma unroll
    for (int it = 0; it < 4; ++it)
        store4h(&xs[0][srow + it * 32][sc2 * 4], v[it]);
    __syncthreads();

    float acc[2][4][4];
#pragma unroll
    for (int mt = 0; mt < 2; ++mt)
#pragma unroll
        for (int nt = 0; nt < 4; ++nt)
#pragma unroll
            for (int q = 0; q < 4; ++q) acc[mt][nt][q] = 0.f;

    for (int kc = 0; kc < NCH; ++kc) {
        const int cur = kc & 1;
        // Prefetch next chunk
        if (kc + 1 < NCH) {
#pragma unroll
            for (int it = 0; it < 4; ++it)
                v[it] = *(const LVec*)&X[(size_t)gr[it] * INDIM + (kc + 1) * 32 + sc2 * 4];
        }
        // Compute current chunk: 2 k16 steps
#pragma unroll
        for (int k16 = 0; k16 < 2; ++k16) {
            const int k0 = k16 * 16;
            const int kg = kc * 32 + k0;
            unsigned a[2][4];
#pragma unroll
            for (int mt = 0; mt < 2; ++mt) {
                int ar = warp_m * 32 + mt * 16 + lr;
                a[mt][0] = *(const unsigned*)&xs[cur][ar][k0 + lc];
                a[mt][1] = *(const unsigned*)&xs[cur][ar + 8][k0 + lc];
                a[mt][2] = *(const unsigned*)&xs[cur][ar][k0 + lc + 8];
                a[mt][3] = *(const unsigned*)&xs[cur][ar + 8][k0 + lc + 8];
            }
            unsigned b[4][2];
#pragma unroll
            for (int nt = 0; nt < 4; ++nt) {
                int bn = warp_n * 32 + nt * 8 + lr;
                b[nt][0] = *(const unsigned*)&ws[bn][kg + lc];
                b[nt][1] = *(const unsigned*)&ws[bn][kg + lc + 8];
            }
#pragma unroll
            for (int mt = 0; mt < 2; ++mt)
#pragma unroll
                for (int nt = 0; nt < 4; ++nt)
                    mma16816(acc[mt][nt][0], acc[mt][nt][1],
                             acc[mt][nt][2], acc[mt][nt][3],
                             a[mt][0], a[mt][1], a[mt][2], a[mt][3],
                             b[nt][0], b[nt][1]);
        }
        // Publish next chunk
        if (kc + 1 < NCH) {
#pragma unroll
            for (int it = 0; it < 4; ++it)
                store4h(&xs[cur ^ 1][srow + it * 32][sc2 * 4], v[it]);
            __syncthreads();
        }
    }

    // Epilogue: fp32 acc -> fp16
#pragma unroll
    for (int mt = 0; mt < 2; ++mt) {
#pragma unroll
        for (int nt = 0; nt < 4; ++nt) {
            int row = row0 + warp_m * 32 + mt * 16 + lr;
            int col = warp_n * 32 + nt * 8 + lc;
            __half2 lo = __floats2half2_rn(acc[mt][nt][0], acc[mt][nt][1]);
            __half2 hi = __floats2half2_rn(acc[mt][nt][2], acc[mt][nt][3]);
            if (row < N)
                *(__half2*)(C + (size_t)row * 64 + col) = lo;
            if (row + 8 < N)
                *(__half2*)(C + (size_t)(row + 8) * 64 + col) = hi;
        }
    }
}

// ---------------------------------------------------------------------------
__global__ void zero_cnt_kernel(int* __restrict__ cnt, int N)
{
    int i = blockIdx.x * blockDim.x + threadIdx.x;
    if (i < N) cnt[i] = 0;
}

// Bucket placement: entry = (src*128) | (weight_bits << 32).
__global__ __launch_bounds__(256) void place_kernel(
    const int* __restrict__ src, const int* __restrict__ dst,
    const float* __restrict__ ew,
    int* __restrict__ cnt, ull* __restrict__ buckets, int E)
{
    int e = blockIdx.x * blockDim.x + threadIdx.x;
    if (e >= E) return;
    int d = dst[e];
    int pos = atomicAdd(&cnt[d], 1);
    if (pos < CAP) {
        ull v = (unsigned)(src[e] * 128)
              | ((ull)__float_as_uint(ew[e]) << 32);
        buckets[(size_t)d * CAP + pos] = v;
    }
}

// Pad each bucket to a multiple of 4 with zero-weight entries.
__global__ void pad_kernel(int* __restrict__ cnt, ull* __restrict__ buckets, int N)
{
    int n = blockIdx.x * blockDim.x + threadIdx.x;
    if (n >= N) return;
    int deg = min(cnt[n], CAP);
    int pdeg = (deg + 3) & ~3;
    ull* b = buckets + (size_t)n * CAP;
#pragma unroll
    for (int i = 0; i < 3; ++i)
        if (deg + i < pdeg) b[deg + i] = 0ULL;
    cnt[n] = pdeg;
}

// ---------------------------------------------------------------------------
// Gather-reduce: 16 lanes per node, 8B (4 halfs) per lane, branchless.
// out = [relu](bias + sum_e w_e * h[src_e]); TOUT = __half (layer1) / float.
// ---------------------------------------------------------------------------
template <bool RELU, typename TOUT>
__global__ __launch_bounds__(256) void gather_reduce_kernel(
    const ull* __restrict__ buckets,
    const int* __restrict__ cnt,
    const __half* __restrict__ h,
    const float* __restrict__ bias,
    TOUT* __restrict__ out, int N)
{
    int node = (blockIdx.x * 256 + threadIdx.x) >> 4;
    int lane = threadIdx.x & 15;
    if (node >= N) return;

    int deg = cnt[node];                 // multiple of 4, <= CAP
    float4 acc = *(const float4*)(bias + lane * 4);
    const ull* b = buckets + (size_t)node * CAP;
    const char* hb = (const char*)h + lane * 8;

    for (int j = 0; j < deg; j += 4) {
#pragma unroll
        for (int k = 0; k < 4; ++k) {
            ull ej = __ldg(&b[j + k]);                   // broadcast across lanes
            float w = __uint_as_float((unsigned)(ej >> 32));
            unsigned off = (unsigned)ej;                  // src*128
            uint2 raw = *(const uint2*)(hb + off);
            __half2 p01 = *(__half2*)&raw.x;
            __half2 p23 = *(__half2*)&raw.y;
            float2 f01 = __half22float2(p01);
            float2 f23 = __half22float2(p23);
            acc.x = fmaf(w, f01.x, acc.x);
            acc.y = fmaf(w, f01.y, acc.y);
            acc.z = fmaf(w, f23.x, acc.z);
            acc.w = fmaf(w, f23.y, acc.w);
        }
    }
    if (RELU) {
        acc.x = fmaxf(acc.x, 0.f); acc.y = fmaxf(acc.y, 0.f);
        acc.z = fmaxf(acc.z, 0.f); acc.w = fmaxf(acc.w, 0.f);
    }
    if (sizeof(TOUT) == 2) {
        store4h((__half*)out + (size_t)node * 64 + lane * 4, acc);
    } else {
        *(float4*)((float*)out + (size_t)node * 64 + lane * 4) = acc;
    }
}

// ---------------------------------------------------------------------------
extern "C" void kernel_launch(void* const* d_in, const int* in_sizes, int n_in,
                              void* d_out, int out_size)
{
    const float* x   = (const float*)d_in[0];
    const int*   ei  = (const int*)d_in[1];
    const float* ew  = (const float*)d_in[2];
    const float* w1  = (const float*)d_in[3];
    const float* b1  = (const float*)d_in[4];
    const float* w2  = (const float*)d_in[5];
    const float* b2  = (const float*)d_in[6];
    float* out = (float*)d_out;

    const int N = in_sizes[0] / 128;       // 100000
    const int E = in_sizes[2];             // 1600000

    __half* bufH = nullptr;
    __half* bufA = nullptr;
    int*    cnt  = nullptr;
    ull*    buckets = nullptr;
    cudaGetSymbolAddress((void**)&bufH, g_bufH);
    cudaGetSymbolAddress((void**)&bufA, g_bufA);
    cudaGetSymbolAddress((void**)&cnt, g_cnt);
    cudaGetSymbolAddress((void**)&buckets, g_buckets);

    const int gemm_blocks = (N + 127) / 128;
    const int gr_blocks   = (N * 16 + 255) / 256;

    // Indexing pass (shared by both layers)
    zero_cnt_kernel<<<(N + 255) / 256, 256>>>(cnt, N);
    place_kernel<<<(E + 255) / 256, 256>>>(ei, ei + E, ew, cnt, buckets, E);
    pad_kernel<<<(N + 255) / 256, 256>>>(cnt, buckets, N);

    // Layer 1: h1 = x@w1 ; agg1 = relu(scatter + b1) stored fp16
    mma_gemm_kernel<128, float><<<gemm_blocks, 256>>>(x, w1, bufH, N);
    gather_reduce_kernel<true, __half><<<gr_blocks, 256>>>(buckets, cnt, bufH, b1, bufA, N);

    // Layer 2: h2 = agg1@w2 ; out = scatter + b2 (fp32)
    mma_gemm_kernel<64, __half><<<gemm_blocks, 256>>>(bufA, w2, bufH, N);
    gather_reduce_kernel<false, float><<<gr_blocks, 256>>>(buckets, cnt, bufH, b2, out, N);
}